// round 9
// baseline (speedup 1.0000x reference)
#include <cuda_runtime.h>

#define TINYV 1.1920929e-7f        // float32 machine eps = np.finfo(float32).eps
#define CGRID 0.49951171875f       // 0.5 - 2^-11, exact in fp32

typedef unsigned long long u64;

// ---- packed f32x2 helpers (sm_103a). Per-lane IEEE RN: bit-identical to scalar. ----
__device__ __forceinline__ u64 pk(float lo, float hi) {
    u64 r; asm("mov.b64 %0, {%1, %2};" : "=l"(r) : "f"(lo), "f"(hi)); return r;
}
__device__ __forceinline__ void upk(u64 v, float& lo, float& hi) {
    asm("mov.b64 {%0, %1}, %2;" : "=f"(lo), "=f"(hi) : "l"(v));
}
__device__ __forceinline__ u64 add2(u64 a, u64 b) {
    u64 r; asm("add.rn.f32x2 %0, %1, %2;" : "=l"(r) : "l"(a), "l"(b)); return r;
}
__device__ __forceinline__ u64 mul2(u64 a, u64 b) {
    u64 r; asm("mul.rn.f32x2 %0, %1, %2;" : "=l"(r) : "l"(a), "l"(b)); return r;
}
__device__ __forceinline__ u64 fma2(u64 a, u64 b, u64 c) {
    u64 r; asm("fma.rn.f32x2 %0, %1, %2, %3;" : "=l"(r) : "l"(a), "l"(b), "l"(c)); return r;
}

// packed-pair constants (bit patterns of (v, v))
#define H2C  0x3F0000003F000000ULL   // (+0.5, +0.5)
#define NH2C 0xBF000000BF000000ULL   // (-0.5, -0.5)
#define M1C  0xBF800000BF800000ULL   // (-1.0, -1.0)
#define M4C  0xC0800000C0800000ULL   // (-4.0, -4.0)
#define QC   0x3E8000003E800000ULL   // (0.25, 0.25)
#define S4C  0x4080000040800000ULL   // (4.0, 4.0)
#define S16C 0x4180000041800000ULL   // (16.0, 16.0)

// -copysign(TINY, x) as a single logic op: (~sign(x)) | bits(2^-23)
__device__ __forceinline__ float negtiny(float x) {
    return __int_as_float(((__float_as_int(x) & 0x80000000) ^ 0x80000000) | 0x34000000);
}

// Literal custom_round (scalar per lane; sequence identical to reference):
// floor((x - copysign(TINY,x)) + 0.5). Packed adds, scalar floor.
__device__ __forceinline__ void cround8_exact(const float x[8], float f[8]) {
#pragma unroll
    for (int p = 0; p < 4; p++) {
        float a0 = x[2*p], a1 = x[2*p+1];
        u64 v = add2(add2(pk(a0, a1), pk(negtiny(a0), negtiny(a1))), H2C);
        float v0, v1; upk(v, v0, v1);
        f[2*p] = floorf(v0); f[2*p+1] = floorf(v1);
    }
}
// Grid custom_round (valid |x| < 2 on >=1/8 grid; validated rel_err=0 in R5/R7):
__device__ __forceinline__ void cround8_grid(const float x[8], float f[8]) {
#pragma unroll
    for (int p = 0; p < 4; p++) {
        float a0 = x[2*p], a1 = x[2*p+1];
        u64 v = add2(pk(a0, a1), pk(copysignf(CGRID, a0), copysignf(CGRID, a1)));
        float v0, v1; upk(v, v0, v1);
        f[2*p] = truncf(v0); f[2*p+1] = truncf(v1);
    }
}

// first-occurrence argmax scan: sel[j] = first j with |e_j|==m; step = sign(e_k),
// fallback (m==0) step = copysign(1, -xa0) (== reference rule).
__device__ __forceinline__ void scanfn(const float e[8], float m, float xa0,
                                       bool sel[8], float& step) {
    bool seen = false;
#pragma unroll
    for (int j = 0; j < 8; j++) {
        bool eq = (fabsf(e[j]) == m);
        sel[j] = eq && !seen;
        seen = seen || eq;
    }
    float t = e[0];
#pragma unroll
    for (int j = 1; j < 8; j++) t = sel[j] ? e[j] : t;
    t = (m == 0.0f) ? -xa0 : t;
    step = copysignf(1.0f, t);
}

// One branch of closest_point_E8 (full R3 replication, packed).
// xa: scalar shifted input; xa2: same, packed; xo2: ORIGINAL x, packed.
// Candidate returned PACKED in yc2; returns distance d (scalar sequential sum).
template<bool GR, bool SHIFTED>
__device__ __forceinline__ float e8_branch(const float xa[8], const u64 xa2[4],
                                           const u64 xo2[4], u64 yc2[4]) {
    float f[8];
    if (GR) cround8_grid(xa, f); else cround8_exact(xa, f);

    u64 f2[4];
    float e[8];
#pragma unroll
    for (int p = 0; p < 4; p++) {
        f2[p] = pk(f[2*p], f[2*p+1]);
        u64 e2 = fma2(f2[p], M1C, xa2[p]);   // e = xa - f (single-rounded subtract)
        upk(e2, e[2*p], e[2*p+1]);
    }

    // parity of sum(f): packed tree (exact small integers -> order-free)
    u64 s = add2(add2(f2[0], f2[1]), add2(f2[2], f2[3]));
    float sl, sh; upk(s, sl, sh);
    bool odd = (((int)(sl + sh)) & 1) != 0;

    // max |e| (FMNMX absorbs |.|)
    float m = fmaxf(fmaxf(fmaxf(fabsf(e[0]),fabsf(e[1])),fmaxf(fabsf(e[2]),fabsf(e[3]))),
                    fmaxf(fmaxf(fabsf(e[4]),fabsf(e[5])),fmaxf(fabsf(e[6]),fabsf(e[7]))));

    bool sel[8]; float step;
    scanfn(e, m, xa[0], sel, step);

    // fold odd into the step ONCE; per-element delta = sel ? step0 : 0.
    // (base + 0.0f is safe: f is never -0.0 under RN, and +-0 outputs are
    //  value-identical downstream.)
    float step0 = odd ? step : 0.0f;

    float d;
    {
        float r[8];
#pragma unroll
        for (int p = 0; p < 4; p++) {
            u64 d2 = pk(sel[2*p] ? step0 : 0.0f, sel[2*p+1] ? step0 : 0.0f);
            u64 base2 = SHIFTED ? add2(f2[p], H2C) : f2[p];
            yc2[p] = add2(base2, d2);                     // candidate, packed
            u64 r2 = fma2(yc2[p], M1C, xo2[p]);           // r = xo - yc
            upk(r2, r[2*p], r[2*p+1]);
        }
        d = r[0] * r[0];
#pragma unroll
        for (int j = 1; j < 8; j++) d = fmaf(r[j], r[j], d);
    }
    return d;
}

// x given both scalar and packed; result packed in y2.
template<bool GR>
__device__ __forceinline__ void cp_e8(const float x[8], const u64 x2[4], u64 y2[4]) {
    float xs[8];
    u64 xs2[4];
#pragma unroll
    for (int p = 0; p < 4; p++) {
        xs2[p] = add2(x2[p], NH2C);                       // x - 0.5 (== scalar)
        upk(xs2[p], xs[2*p], xs[2*p+1]);
    }
    u64 yA2[4], yB2[4];
    float dA = e8_branch<GR, false>(x,  x2,  x2, yA2);
    float dB = e8_branch<GR, true >(xs, xs2, x2, yB2);
    bool pickA = dA < dB;                                 // tie -> B (matches reference)
#pragma unroll
    for (int p = 0; p < 4; p++) y2[p] = pickA ? yA2[p] : yB2[p];
}

__global__ __launch_bounds__(128, 6)   // cap regs ~85 -> 6 blocks = 24 warps/SM
void LatticeQuantizer_kernel(const float* __restrict__ x,
                             const float* __restrict__ beta_p,
                             const float* __restrict__ eps,
                             float* __restrict__ out, int N)
{
    int i = blockIdx.x * blockDim.x + threadIdx.x;
    if (i >= N) return;

    float beta = __ldg(beta_p);
    float4 ea = __ldg((const float4*)eps);
    float4 eb = __ldg((const float4*)eps + 1);
    u64 ev2[4] = { pk(ea.x, ea.y), pk(ea.z, ea.w), pk(eb.x, eb.y), pk(eb.z, eb.w) };

    float4 va = ((const float4*)x)[2 * i];
    float4 vb = ((const float4*)x)[2 * i + 1];
    float xl[8] = {va.x, va.y, va.z, va.w, vb.x, vb.y, vb.z, vb.w};
#pragma unroll
    for (int j = 0; j < 8; j++) xl[j] = __fdiv_rn(xl[j], beta);  // IEEE div under fast_math
    u64 xl2[4];
#pragma unroll
    for (int p = 0; p < 4; p++) xl2[p] = pk(xl[2*p], xl[2*p+1]);

    u64 xh2[4];

#pragma unroll
    for (int m = 0; m < 3; m++) {
        // ---- encode: yq = closest_point_E8(xl + eps) ----
        float xe[8];
        u64 xe2[4], yq2[4];
#pragma unroll
        for (int p = 0; p < 4; p++) {
            xe2[p] = add2(xl2[p], ev2[p]);
            upk(xe2[p], xe[2*p], xe[2*p+1]);
        }
        // layer 0: continuous; layer 1: |xe| can exceed 2 -> exact cround.
        // layer 2: 1/8 grid, |xe| < 2 -> grid cround (validated).
        if (m < 2) cp_e8<false>(xe, xe2, yq2);
        else       cp_e8<true >(xe, xe2, yq2);

        float yq[8];
#pragma unroll
        for (int p = 0; p < 4; p++) upk(yq2[p], yq[2*p], yq[2*p+1]);

        // ---- acc = yq @ G_inv via exact forward substitution (acc @ Gm = yq) ----
        float a[8];
        a[0] = 0.5f * yq[0];
#pragma unroll
        for (int j = 1; j < 7; j++) a[j] = a[j - 1] + yq[j];
        float s06 = ((a[0] + a[1]) + (a[2] + a[3])) + ((a[4] + a[5]) + a[6]);
        a[7] = fmaf(2.0f, yq[7], -s06);

        // ---- b = custom_round(fmod(acc,4)): quarter-int in (-4,4), ties at
        //      +-2.5/+-3.5 round half-up -> exact cround required ----
        float r8[8], bv[8];
#pragma unroll
        for (int j = 0; j < 8; j++)
            r8[j] = fmaf(-4.0f, truncf(a[j] * 0.25f), a[j]);  // == fmodf(a,4) exactly
        cround8_exact(r8, bv);

        // ---- next layer input: xl = yq * 0.25 (packed, exact) ----
#pragma unroll
        for (int p = 0; p < 4; p++) {
            xl2[p] = mul2(yq2[p], QC);
            upk(xl2[p], xl[2*p], xl[2*p+1]);
        }

        // ---- Gb = b @ G.T, sparse exact form ----
        float gb[8];
        {
            float h = 0.5f * bv[7];
            gb[0] = fmaf(2.0f, bv[0], -bv[1]) + h;
#pragma unroll
            for (int j = 1; j < 6; j++) gb[j] = (bv[j] - bv[j + 1]) + h;
            gb[6] = bv[6] + h;
            gb[7] = h;
        }

        // ---- x_i = Gb - 4*closest_point_E8(Gb/4);  xh += 4^m * x_i ----
        // gq in [-0.75, 1.875], branch-B in [-1.25, 1.375]: grid cround valid.
        float gq[8];
        u64 gb2[4], gq2[4], cpv2[4];
#pragma unroll
        for (int p = 0; p < 4; p++) {
            gb2[p] = pk(gb[2*p], gb[2*p+1]);
            gq2[p] = mul2(gb2[p], QC);
            upk(gq2[p], gq[2*p], gq[2*p+1]);
        }
        cp_e8<true>(gq, gq2, cpv2);

#pragma unroll
        for (int p = 0; p < 4; p++) {
            u64 xi = fma2(cpv2[p], M4C, gb2[p]);           // exact dyadic
            if (m == 0)      xh2[p] = xi;
            else if (m == 1) xh2[p] = fma2(xi, S4C,  xh2[p]);
            else             xh2[p] = fma2(xi, S16C, xh2[p]);
        }
    }

    u64 bb = pk(beta, beta);
    float o[8];
#pragma unroll
    for (int p = 0; p < 4; p++) {
        u64 t = mul2(xh2[p], bb);
        upk(t, o[2*p], o[2*p+1]);
    }
    float4 o0 = {o[0], o[1], o[2], o[3]};
    float4 o1 = {o[4], o[5], o[6], o[7]};
    ((float4*)out)[2 * i]     = o0;
    ((float4*)out)[2 * i + 1] = o1;
}

extern "C" void kernel_launch(void* const* d_in, const int* in_sizes, int n_in,
                              void* d_out, int out_size) {
    const float* x    = (const float*)d_in[0];
    const float* beta = (const float*)d_in[1];
    const float* eps  = (const float*)d_in[4];
    float* out = (float*)d_out;

    int N = in_sizes[0] / 8;
    int threads = 128;
    int blocks = (N + threads - 1) / threads;
    LatticeQuantizer_kernel<<<blocks, threads>>>(x, beta, eps, out, N);
}